// round 5
// baseline (speedup 1.0000x reference)
#include <cuda_runtime.h>

// DynamicNet_17695265259799 — exact closed form of the reference.
//
// reference(): Wm = tril(W,-1) keeps W[i,j] only for i > j, but the scan
// fills nodes j = 1..n-1 in ASCENDING order, so at step j every potential
// source activation A[:,i], i > j is still exactly 0.0f. Hence
// s_j == b[j] exactly (0 * finite == 0 in IEEE fp32), the output node is
// linear, and the result is b[n-1] broadcast over the batch — independent
// of x and W for all finite inputs.
//
// R5: measured CTA-shape sweep — 1024x256 / 1 STG.128 per thread is the
// optimum (4.22us); 256x256x4 = 4.61, 2048x128 = 6.08. Kernel time is
// T_ovh(~5000cyc launch ramp) + store drain(~670cyc) bound; this version
// just trims per-thread instructions to sit exactly on that floor.

__global__ __launch_bounds__(256)
void dynamicnet_broadcast_kernel(const float* __restrict__ bias_last,
                                 float4* __restrict__ out4,
                                 int n4) {
    const float v = __ldg(bias_last);                      // broadcast scalar
    const int tid = blockIdx.x * blockDim.x + threadIdx.x; // overlaps LDG
    if (tid < n4) out4[tid] = make_float4(v, v, v, v);     // one STG.128
}

// Generic tail (out_size % 4 != 0) — never launched for out_size = 1048576.
__global__ void dynamicnet_tail_kernel(const float* __restrict__ bias_last,
                                       float* __restrict__ out,
                                       int start, int out_elems) {
    const float v = __ldg(bias_last);
    const int i = start + threadIdx.x;
    if (i < out_elems) out[i] = v;
}

extern "C" void kernel_launch(void* const* d_in, const int* in_sizes, int n_in,
                              void* d_out, int out_size) {
    // metadata order: x [BATCH,1] f32, W [n,n] f32, b [n] f32
    const float* bias = (const float*)d_in[2];
    const float* bias_last = bias + (in_sizes[2] - 1);  // &b[65]

    float* out = (float*)d_out;
    const int n4 = out_size >> 2;  // 262144 float4 slots

    const int threads = 256;
    int blocks = (n4 + threads - 1) / threads;  // 1024 — measured optimum
    if (blocks < 1) blocks = 1;

    dynamicnet_broadcast_kernel<<<blocks, threads>>>(
        bias_last, reinterpret_cast<float4*>(out), n4);

    const int tail = out_size - (n4 << 2);
    if (tail > 0) {
        dynamicnet_tail_kernel<<<1, 32>>>(bias_last, out, n4 << 2, out_size);
    }
}